// round 7
// baseline (speedup 1.0000x reference)
#include <cuda_runtime.h>

#define EPS 1e-6f
#define BLOCK 128
#define WARPS (BLOCK / 32)
#define ROWPAD 25              // odd stride => conflict-free per-row LDS
#define TILES 2                // rows per CTA = TILES*BLOCK
#define MAX_PARTIALS 8192

__device__ float2 g_partials[MAX_PARTIALS];
__device__ unsigned int g_count = 0;

__device__ __forceinline__ float norm2f(float x, float y) {
    return sqrtf(x * x + y * y);
}

// Per-row loss from a 24-float row view (any stride-1 float pointer).
__device__ __forceinline__ void row_loss(const float* __restrict__ P,
                                         const float* __restrict__ G,
                                         float& L, float& cnt)
{
    float px[4], py[4], gx[4], gy[4];
    int nv = 0;
    #pragma unroll
    for (int k = 0; k < 8; k++) {
        const float ax = P[3*k], ay = P[3*k+1], az = P[3*k+2];
        const float bx = G[3*k], by = G[3*k+1], bz = G[3*k+2];
        const bool vis = (az > 0.5f) && (bz > 0.5f);
        if (vis) {
            if (nv == 0)      { px[0]=ax; py[0]=ay; gx[0]=bx; gy[0]=by; }
            else if (nv == 1) { px[1]=ax; py[1]=ay; gx[1]=bx; gy[1]=by; }
            else if (nv == 2) { px[2]=ax; py[2]=ay; gx[2]=bx; gy[2]=by; }
            else if (nv == 3) { px[3]=ax; py[3]=ay; gx[3]=bx; gy[3]=by; }
            nv++;
        }
    }
    if (nv < 4) return;

    const float pred_cr = __fdividef(norm2f(px[2]-px[0], py[2]-py[0]),
                                     norm2f(px[3]-px[1], py[3]-py[1]) + EPS);
    const float gt_cr   = __fdividef(norm2f(gx[2]-gx[0], gy[2]-gy[0]),
                                     norm2f(gx[3]-gx[1], gy[3]-gy[1]) + EPS);
    const float L_shape = fabsf(pred_cr - gt_cr);

    const float v12x = px[1]-px[0], v12y = py[1]-py[0];
    const float v23x = px[2]-px[1], v23y = py[2]-py[1];
    const float v34x = px[3]-px[2], v34y = py[3]-py[2];
    const float v41x = px[0]-px[3], v41y = py[0]-py[3];
    const float l12 = norm2f(v12x, v12y);
    const float l23 = norm2f(v23x, v23y);
    const float l34 = norm2f(v34x, v34y);
    const float l41 = norm2f(v41x, v41y);

    const float par1 = __fdividef(fabsf(l12 - l34), l12 + l34 + EPS);
    const float par2 = __fdividef(fabsf(l23 - l41), l23 + l41 + EPS);
    const float dot1 = fabsf(__fdividef(v12x*v41x + v12y*v41y, l12*l41 + EPS));
    const float dot2 = fabsf(__fdividef(v12x*v23x + v12y*v23y, l12*l23 + EPS));
    const float dot3 = fabsf(__fdividef(v23x*v34x + v23y*v34y, l23*l34 + EPS));
    const float dot4 = fabsf(__fdividef(v34x*v41x + v34y*v41y, l34*l41 + EPS));
    const float L_edge = (par1 + par2) * 0.5f + (dot1 + dot2 + dot3 + dot4) * 0.25f;

    float dist = 0.0f;
    #pragma unroll
    for (int i = 0; i < 4; i++)
        dist += norm2f(px[i]-gx[i], py[i]-gy[i]);
    dist *= 0.25f;

    const float pax1 = px[1]-px[0], pay1 = py[1]-py[0];
    const float pax2 = px[2]-px[0], pay2 = py[2]-py[0];
    const float pax3 = px[3]-px[0], pay3 = py[3]-py[0];
    const float pred_area = 0.5f * fabsf(pax1*pay2 - pay1*pax2)
                          + 0.5f * fabsf(pax2*pay3 - pay2*pax3);
    const float gax1 = gx[1]-gx[0], gay1 = gy[1]-gy[0];
    const float gax2 = gx[2]-gx[0], gay2 = gy[2]-gy[0];
    const float gax3 = gx[3]-gx[0], gay3 = gy[3]-gy[0];
    const float gt_area = 0.5f * fabsf(gax1*gay2 - gay1*gax2)
                        + 0.5f * fabsf(gax2*gay3 - gay2*gax3);
    const float area_ratio = __fdividef(fabsf(pred_area - gt_area), gt_area + EPS);

    const float pmx = 0.25f * (px[0]+px[1]+px[2]+px[3]);
    const float pmy = 0.25f * (py[0]+py[1]+py[2]+py[3]);
    const float gmx = 0.25f * (gx[0]+gx[1]+gx[2]+gx[3]);
    const float gmy = 0.25f * (gy[0]+gy[1]+gy[2]+gy[3]);
    float rel_cons = 0.0f;
    #pragma unroll
    for (int i = 0; i < 4; i++)
        rel_cons += norm2f((px[i]-pmx) - (gx[i]-gmx),
                           (py[i]-pmy) - (gy[i]-gmy));
    rel_cons *= 0.25f;

    const float L_pos = 0.4f * dist + 0.3f * area_ratio + 0.3f * rel_cons;

    L   += 0.4f * L_shape + 0.3f * L_edge + 0.3f * L_pos;
    cnt += 1.0f;
}

__global__ void __launch_bounds__(BLOCK, 8)
gsc_fused_kernel(const float* __restrict__ pred,
                 const float* __restrict__ gt,
                 float* __restrict__ out,
                 int nrows)
{
    __shared__ float smP[BLOCK * ROWPAD];   // 12.8 KB
    __shared__ float smG[BLOCK * ROWPAD];   // 12.8 KB
    __shared__ float sL[WARPS];
    __shared__ float sC[WARPS];
    __shared__ int sIsLast;

    const int tid  = threadIdx.x;
    const int warp = tid >> 5;
    const int lane = tid & 31;

    float L = 0.0f, cnt = 0.0f;

    #pragma unroll
    for (int t = 0; t < TILES; t++) {
        const int tilebase = (blockIdx.x * TILES + t) * BLOCK;   // first row of tile

        if (tilebase + BLOCK <= nrows) {
            // ---- fast path: per-warp coalesced stage ----
            // Warp covers rows [tilebase + warp*32, +32). 192 float4 per tensor.
            const float4* p4 = reinterpret_cast<const float4*>(pred)
                             + (size_t)(tilebase + warp * 32) * 6;
            const float4* q4 = reinterpret_cast<const float4*>(gt)
                             + (size_t)(tilebase + warp * 32) * 6;

            float4 rp[6], rg[6];
            #pragma unroll
            for (int i = 0; i < 6; i++) rp[i] = p4[lane + 32 * i];
            #pragma unroll
            for (int i = 0; i < 6; i++) rg[i] = q4[lane + 32 * i];

            const int wbase = warp * 32 * ROWPAD;
            #pragma unroll
            for (int i = 0; i < 6; i++) {
                const int j = lane + 32 * i;
                const int w = wbase + (j / 6) * ROWPAD + (j % 6) * 4;
                smP[w + 0] = rp[i].x; smP[w + 1] = rp[i].y;
                smP[w + 2] = rp[i].z; smP[w + 3] = rp[i].w;
                smG[w + 0] = rg[i].x; smG[w + 1] = rg[i].y;
                smG[w + 2] = rg[i].z; smG[w + 3] = rg[i].w;
            }
            __syncwarp();

            row_loss(&smP[tid * ROWPAD], &smG[tid * ROWPAD], L, cnt);
            __syncwarp();   // protect region before next tile's STS
        } else {
            // ---- ragged tail: direct strided loads, bounds-checked ----
            const int row = tilebase + tid;
            if (row < nrows) {
                float pv[24], gv[24];
                const float4* p4 = reinterpret_cast<const float4*>(pred + (size_t)row * 24);
                const float4* q4 = reinterpret_cast<const float4*>(gt   + (size_t)row * 24);
                #pragma unroll
                for (int i = 0; i < 6; i++) {
                    float4 a = p4[i];
                    pv[4*i+0]=a.x; pv[4*i+1]=a.y; pv[4*i+2]=a.z; pv[4*i+3]=a.w;
                    float4 b = q4[i];
                    gv[4*i+0]=b.x; gv[4*i+1]=b.y; gv[4*i+2]=b.z; gv[4*i+3]=b.w;
                }
                row_loss(pv, gv, L, cnt);
            }
        }
    }

    // ---- block reduction (deterministic tree) ----
    #pragma unroll
    for (int off = 16; off > 0; off >>= 1) {
        L   += __shfl_down_sync(0xffffffffu, L,   off);
        cnt += __shfl_down_sync(0xffffffffu, cnt, off);
    }
    if (lane == 0) { sL[warp] = L; sC[warp] = cnt; }
    __syncthreads();
    if (tid == 0) {
        float tL = 0.0f, tC = 0.0f;
        #pragma unroll
        for (int w = 0; w < WARPS; w++) { tL += sL[w]; tC += sC[w]; }
        g_partials[blockIdx.x] = make_float2(tL, tC);
        __threadfence();
        const unsigned int old = atomicAdd(&g_count, 1u);
        sIsLast = (old == gridDim.x - 1) ? 1 : 0;
    }
    __syncthreads();

    // ---- last block: final reduction (fixed order -> deterministic) ----
    if (sIsLast) {
        float fL = 0.0f, fC = 0.0f;
        const int nblocks = gridDim.x;
        for (int i = tid; i < nblocks; i += BLOCK) {
            float2 v = g_partials[i];
            fL += v.x;
            fC += v.y;
        }
        #pragma unroll
        for (int off = 16; off > 0; off >>= 1) {
            fL += __shfl_down_sync(0xffffffffu, fL, off);
            fC += __shfl_down_sync(0xffffffffu, fC, off);
        }
        if (lane == 0) { sL[warp] = fL; sC[warp] = fC; }
        __syncthreads();
        if (tid == 0) {
            float tL = 0.0f, tC = 0.0f;
            #pragma unroll
            for (int w = 0; w < WARPS; w++) { tL += sL[w]; tC += sC[w]; }
            out[0] = (tC > 0.5f) ? (tL / tC) : 0.0f;
            g_count = 0;   // reset for next graph replay
        }
    }
}

extern "C" void kernel_launch(void* const* d_in, const int* in_sizes, int n_in,
                              void* d_out, int out_size)
{
    const float* pred = (const float*)d_in[0];
    const float* gt   = (const float*)d_in[1];
    float* out = (float*)d_out;

    const int nrows = in_sizes[0] / 24;                   // 524288
    const int rows_per_cta = BLOCK * TILES;               // 256
    int nblocks = (nrows + rows_per_cta - 1) / rows_per_cta;   // 2048
    if (nblocks > MAX_PARTIALS) nblocks = MAX_PARTIALS;

    gsc_fused_kernel<<<nblocks, BLOCK>>>(pred, gt, out, nrows);
}